// round 2
// baseline (speedup 1.0000x reference)
#include <cuda_runtime.h>
#include <math.h>

#define N_TOK 131072
#define DIM   256
#define GH    128
#define NE    8
#define H1    256
#define H2    128
#define NOUT  10

// ---------------- scratch (no allocations allowed) ----------------
__device__ int   g_cnt[NE];
__device__ int   g_idx[NE * N_TOK];
__device__ float g_wgt[NE * N_TOK];

__device__ __forceinline__ float gelu_exact(float v) {
    return 0.5f * v * (1.0f + erff(v * 0.70710678118654752f));
}

// reduce across a half-warp (16 lanes); xor masks stay within the 16-group
__device__ __forceinline__ float hwred(float v) {
    v += __shfl_xor_sync(0xffffffffu, v, 1);
    v += __shfl_xor_sync(0xffffffffu, v, 2);
    v += __shfl_xor_sync(0xffffffffu, v, 4);
    v += __shfl_xor_sync(0xffffffffu, v, 8);
    return v;
}

// ---------------- zero output + counters ----------------
// y has N_TOK*NOUT = 1,310,720 floats (even) -> float2 stores
__global__ __launch_bounds__(256) void k_zero(float* __restrict__ y) {
    int i = blockIdx.x * blockDim.x + threadIdx.x;
    if (i < (N_TOK * NOUT) / 2) ((float2*)y)[i] = make_float2(0.0f, 0.0f);
    if (i < NE) g_cnt[i] = 0;
}

// ---------------- gate: LN(x@gW1+b) -> gelu -> @gW2+b -> /T -> top2 -> scatter ----------------
// block = 256 threads, 64 tokens. smem: xs[64][260] | ws[32*128] | lgs[512]
__global__ __launch_bounds__(256, 2) void k_gate(
    const float* __restrict__ x,
    const float* __restrict__ gW1, const float* __restrict__ gb1,
    const float* __restrict__ glng, const float* __restrict__ glnb,
    const float* __restrict__ gW2, const float* __restrict__ gb2,
    const float* __restrict__ temp)
{
    extern __shared__ float sm[];
    float* xs  = sm;             // 64*260 = 16640 floats (x tile, later g tile)
    float* ws  = xs + 64 * 260;  // 4096 floats (W1 chunk / gW2)
    float* lgs = ws + 32 * 128;  // 512 floats (logits [64][8])

    const int tid  = threadIdx.x;
    const int tok0 = blockIdx.x * 64;

    // load x tile coalesced: 64 rows x 256 floats
    for (int i = tid; i < 4096; i += 256) {
        int r = i >> 6, c = i & 63;
        *(float4*)(xs + r * 260 + c * 4) =
            *(const float4*)(x + (size_t)(tok0 + r) * DIM + c * 4);
    }

    const int ty = tid >> 4, tx = tid & 15;
    const int t0 = ty * 4;

    float acc[4][8];
#pragma unroll
    for (int i = 0; i < 4; i++)
#pragma unroll
        for (int j = 0; j < 8; j++) acc[i][j] = 0.0f;

    const float* xr = xs + t0 * 260;
    for (int kc = 0; kc < DIM; kc += 32) {
        __syncthreads();
        const float4* wsrc = (const float4*)(gW1 + (size_t)kc * GH);
        for (int i = tid; i < 1024; i += 256) ((float4*)ws)[i] = wsrc[i];
        __syncthreads();
#pragma unroll 8
        for (int k = 0; k < 32; k++) {
            float a0 = xr[0 * 260 + kc + k];
            float a1 = xr[1 * 260 + kc + k];
            float a2 = xr[2 * 260 + kc + k];
            float a3 = xr[3 * 260 + kc + k];
            const float* wr = ws + k * GH + tx * 8;
#pragma unroll
            for (int j4 = 0; j4 < 2; j4++) {
                float4 b = *(const float4*)(wr + 4 * j4);
                acc[0][4*j4+0] += a0 * b.x; acc[0][4*j4+1] += a0 * b.y;
                acc[0][4*j4+2] += a0 * b.z; acc[0][4*j4+3] += a0 * b.w;
                acc[1][4*j4+0] += a1 * b.x; acc[1][4*j4+1] += a1 * b.y;
                acc[1][4*j4+2] += a1 * b.z; acc[1][4*j4+3] += a1 * b.w;
                acc[2][4*j4+0] += a2 * b.x; acc[2][4*j4+1] += a2 * b.y;
                acc[2][4*j4+2] += a2 * b.z; acc[2][4*j4+3] += a2 * b.w;
                acc[3][4*j4+0] += a3 * b.x; acc[3][4*j4+1] += a3 * b.y;
                acc[3][4*j4+2] += a3 * b.z; acc[3][4*j4+3] += a3 * b.w;
            }
        }
    }
    __syncthreads();  // all xs reads done before overwrite

    // bias + LN + gelu -> store g into xs (stride 260, cols 0..127)
    {
        const int c0 = tx * 8;
        float bia[8], gga[8], bba[8];
        float4 v;
        v = *(const float4*)(gb1 + c0);     bia[0]=v.x; bia[1]=v.y; bia[2]=v.z; bia[3]=v.w;
        v = *(const float4*)(gb1 + c0 + 4); bia[4]=v.x; bia[5]=v.y; bia[6]=v.z; bia[7]=v.w;
        v = *(const float4*)(glng + c0);     gga[0]=v.x; gga[1]=v.y; gga[2]=v.z; gga[3]=v.w;
        v = *(const float4*)(glng + c0 + 4); gga[4]=v.x; gga[5]=v.y; gga[6]=v.z; gga[7]=v.w;
        v = *(const float4*)(glnb + c0);     bba[0]=v.x; bba[1]=v.y; bba[2]=v.z; bba[3]=v.w;
        v = *(const float4*)(glnb + c0 + 4); bba[4]=v.x; bba[5]=v.y; bba[6]=v.z; bba[7]=v.w;
#pragma unroll
        for (int i = 0; i < 4; i++) {
            float s = 0.0f;
#pragma unroll
            for (int j = 0; j < 8; j++) { acc[i][j] += bia[j]; s += acc[i][j]; }
            s = hwred(s);
            float mean = s * (1.0f / 128.0f);
            float vs = 0.0f;
#pragma unroll
            for (int j = 0; j < 8; j++) { float d = acc[i][j] - mean; vs += d * d; }
            vs = hwred(vs);
            float inv = rsqrtf(vs * (1.0f / 128.0f) + 1e-5f);
#pragma unroll
            for (int j = 0; j < 8; j++) {
                float u = (acc[i][j] - mean) * inv * gga[j] + bba[j];
                xs[(t0 + i) * 260 + c0 + j] = gelu_exact(u);
            }
        }
    }
    __syncthreads();

    // gW2 -> ws (1024 floats)
    for (int i = tid; i < 256; i += 256) ((float4*)ws)[i] = ((const float4*)gW2)[i];
    __syncthreads();

    const float tt = fminf(fmaxf(temp[0], 0.5f), 5.0f);
    for (int o = tid; o < 512; o += 256) {
        int t = o >> 3, e = o & 7;
        const float* gr = xs + t * 260;
        float s = 0.0f;
#pragma unroll 8
        for (int k = 0; k < GH; k++) s += gr[k] * ws[k * NE + e];
        lgs[o] = (s + gb2[e]) / tt;
    }
    __syncthreads();

    // top-2, softmax, renorm, scatter to expert lists
    if (tid < 64) {
        float v[NE];
#pragma unroll
        for (int e = 0; e < NE; e++) v[e] = lgs[tid * NE + e];
        int i0 = 0; float b0 = v[0];
#pragma unroll
        for (int e = 1; e < NE; e++) if (v[e] > b0) { b0 = v[e]; i0 = e; }
        int i1 = -1; float b1 = -3.4e38f;
#pragma unroll
        for (int e = 0; e < NE; e++) if (e != i0 && v[e] > b1) { b1 = v[e]; i1 = e; }
        float e1 = expf(b1 - b0);
        float s = 1.0f + e1;
        float p0 = 1.0f / s, p1 = e1 / s;
        float den = p0 + p1 + 1e-10f;
        float w0 = p0 / den, w1 = p1 / den;
        int token = tok0 + tid;
        int p = atomicAdd(&g_cnt[i0], 1);
        g_idx[i0 * N_TOK + p] = token; g_wgt[i0 * N_TOK + p] = w0;
        p = atomicAdd(&g_cnt[i1], 1);
        g_idx[i1 * N_TOK + p] = token; g_wgt[i1 * N_TOK + p] = w1;
    }
}

// ---------------- expert: fused 3-layer MLP over 64 gathered tokens ----------------
// smem: xs[64][260] | wbuf[8512] (W chunk / h2[64][132]) | w3s[1280] | w3b[16] | swt[64] | sidx[64]
__global__ __launch_bounds__(256, 2) void k_expert(
    const float* __restrict__ x,
    const float* __restrict__ eW1, const float* __restrict__ eb1,
    const float* __restrict__ l1g, const float* __restrict__ l1b,
    const float* __restrict__ eW2, const float* __restrict__ eb2,
    const float* __restrict__ l2g, const float* __restrict__ l2b,
    const float* __restrict__ eW3, const float* __restrict__ eb3,
    float* __restrict__ y)
{
    const int e   = blockIdx.y;
    const int cnt = g_cnt[e];
    const int tile = blockIdx.x;
    if (tile * 64 >= cnt) return;

    extern __shared__ float sm[];
    float* xs   = sm;               // 16640
    float* wbuf = xs + 16640;       // 8512
    float* w3s  = wbuf + 8512;      // 1280
    float* w3b  = w3s + 1280;       // 16
    float* swt  = w3b + 16;         // 64
    int*   sidx = (int*)(swt + 64); // 64

    const int tid = threadIdx.x;

    if (tid < 64) {
        int p  = tile * 64 + tid;
        int pp = p < cnt ? p : cnt - 1;
        sidx[tid] = g_idx[e * N_TOK + pp];
        swt[tid]  = (p < cnt) ? g_wgt[e * N_TOK + pp] : 0.0f;
    }
    for (int i = tid; i < 320; i += 256)
        ((float4*)w3s)[i] = ((const float4*)(eW3 + (size_t)e * H2 * NOUT))[i];
    if (tid < NOUT) w3b[tid] = eb3[e * NOUT + tid];
    __syncthreads();

    // gather x rows
    for (int i = tid; i < 4096; i += 256) {
        int r = i >> 6, c = i & 63;
        *(float4*)(xs + r * 260 + c * 4) =
            *(const float4*)(x + (size_t)sidx[r] * DIM + c * 4);
    }

    const int ty = tid >> 4, tx = tid & 15;
    const int t0 = ty * 4;
    const float* xr = xs + t0 * 260;

    // ---- layer 1: [64,256] = x[64,256] @ W1[256,256] ----
    float acc[4][16];
#pragma unroll
    for (int i = 0; i < 4; i++)
#pragma unroll
        for (int j = 0; j < 16; j++) acc[i][j] = 0.0f;

    for (int kc = 0; kc < DIM; kc += 32) {
        __syncthreads();
        const float4* wsrc = (const float4*)(eW1 + ((size_t)e * DIM + kc) * H1);
        for (int i = tid; i < 2048; i += 256) ((float4*)wbuf)[i] = wsrc[i];
        __syncthreads();
#pragma unroll 4
        for (int k = 0; k < 32; k++) {
            float a0 = xr[0 * 260 + kc + k];
            float a1 = xr[1 * 260 + kc + k];
            float a2 = xr[2 * 260 + kc + k];
            float a3 = xr[3 * 260 + kc + k];
            const float* wr = wbuf + k * H1 + tx * 16;
#pragma unroll
            for (int j4 = 0; j4 < 4; j4++) {
                float4 b = *(const float4*)(wr + 4 * j4);
                acc[0][4*j4+0] += a0 * b.x; acc[0][4*j4+1] += a0 * b.y;
                acc[0][4*j4+2] += a0 * b.z; acc[0][4*j4+3] += a0 * b.w;
                acc[1][4*j4+0] += a1 * b.x; acc[1][4*j4+1] += a1 * b.y;
                acc[1][4*j4+2] += a1 * b.z; acc[1][4*j4+3] += a1 * b.w;
                acc[2][4*j4+0] += a2 * b.x; acc[2][4*j4+1] += a2 * b.y;
                acc[2][4*j4+2] += a2 * b.z; acc[2][4*j4+3] += a2 * b.w;
                acc[3][4*j4+0] += a3 * b.x; acc[3][4*j4+1] += a3 * b.y;
                acc[3][4*j4+2] += a3 * b.z; acc[3][4*j4+3] += a3 * b.w;
            }
        }
    }
    __syncthreads();  // xs reads done; safe to overwrite with h1

    // ---- LN1 + gelu -> xs ----
    {
        const int c0 = tx * 16;
        float bia[16], gga[16], bba[16];
#pragma unroll
        for (int q = 0; q < 4; q++) {
            float4 v;
            v = *(const float4*)(eb1 + e * H1 + c0 + 4 * q);
            bia[4*q]=v.x; bia[4*q+1]=v.y; bia[4*q+2]=v.z; bia[4*q+3]=v.w;
            v = *(const float4*)(l1g + e * H1 + c0 + 4 * q);
            gga[4*q]=v.x; gga[4*q+1]=v.y; gga[4*q+2]=v.z; gga[4*q+3]=v.w;
            v = *(const float4*)(l1b + e * H1 + c0 + 4 * q);
            bba[4*q]=v.x; bba[4*q+1]=v.y; bba[4*q+2]=v.z; bba[4*q+3]=v.w;
        }
#pragma unroll
        for (int i = 0; i < 4; i++) {
            float s = 0.0f;
#pragma unroll
            for (int j = 0; j < 16; j++) { acc[i][j] += bia[j]; s += acc[i][j]; }
            s = hwred(s);
            float mean = s * (1.0f / 256.0f);
            float vs = 0.0f;
#pragma unroll
            for (int j = 0; j < 16; j++) { float d = acc[i][j] - mean; vs += d * d; }
            vs = hwred(vs);
            float inv = rsqrtf(vs * (1.0f / 256.0f) + 1e-5f);
#pragma unroll
            for (int j = 0; j < 16; j++) {
                float u = (acc[i][j] - mean) * inv * gga[j] + bba[j];
                xs[(t0 + i) * 260 + c0 + j] = gelu_exact(u);
            }
        }
    }

    // ---- layer 2: [64,128] = h1[64,256] @ W2[256,128] ----
    float a2c[4][8];
#pragma unroll
    for (int i = 0; i < 4; i++)
#pragma unroll
        for (int j = 0; j < 8; j++) a2c[i][j] = 0.0f;

    for (int kc = 0; kc < H1; kc += 32) {
        __syncthreads();
        const float4* wsrc = (const float4*)(eW2 + ((size_t)e * H1 + kc) * H2);
        for (int i = tid; i < 1024; i += 256) ((float4*)wbuf)[i] = wsrc[i];
        __syncthreads();
#pragma unroll 8
        for (int k = 0; k < 32; k++) {
            float a0 = xr[0 * 260 + kc + k];
            float a1 = xr[1 * 260 + kc + k];
            float a2 = xr[2 * 260 + kc + k];
            float a3 = xr[3 * 260 + kc + k];
            const float* wr = wbuf + k * H2 + tx * 8;
#pragma unroll
            for (int j4 = 0; j4 < 2; j4++) {
                float4 b = *(const float4*)(wr + 4 * j4);
                a2c[0][4*j4+0] += a0 * b.x; a2c[0][4*j4+1] += a0 * b.y;
                a2c[0][4*j4+2] += a0 * b.z; a2c[0][4*j4+3] += a0 * b.w;
                a2c[1][4*j4+0] += a1 * b.x; a2c[1][4*j4+1] += a1 * b.y;
                a2c[1][4*j4+2] += a1 * b.z; a2c[1][4*j4+3] += a1 * b.w;
                a2c[2][4*j4+0] += a2 * b.x; a2c[2][4*j4+1] += a2 * b.y;
                a2c[2][4*j4+2] += a2 * b.z; a2c[2][4*j4+3] += a2 * b.w;
                a2c[3][4*j4+0] += a3 * b.x; a2c[3][4*j4+1] += a3 * b.y;
                a2c[3][4*j4+2] += a3 * b.z; a2c[3][4*j4+3] += a3 * b.w;
            }
        }
    }
    __syncthreads();  // wbuf reads done; safe to overwrite with h2

    // ---- LN2 + gelu -> h2 in wbuf (stride 132) ----
    {
        const int c0 = tx * 8;
        float bia[8], gga[8], bba[8];
#pragma unroll
        for (int q = 0; q < 2; q++) {
            float4 v;
            v = *(const float4*)(eb2 + e * H2 + c0 + 4 * q);
            bia[4*q]=v.x; bia[4*q+1]=v.y; bia[4*q+2]=v.z; bia[4*q+3]=v.w;
            v = *(const float4*)(l2g + e * H2 + c0 + 4 * q);
            gga[4*q]=v.x; gga[4*q+1]=v.y; gga[4*q+2]=v.z; gga[4*q+3]=v.w;
            v = *(const float4*)(l2b + e * H2 + c0 + 4 * q);
            bba[4*q]=v.x; bba[4*q+1]=v.y; bba[4*q+2]=v.z; bba[4*q+3]=v.w;
        }
#pragma unroll
        for (int i = 0; i < 4; i++) {
            float s = 0.0f;
#pragma unroll
            for (int j = 0; j < 8; j++) { a2c[i][j] += bia[j]; s += a2c[i][j]; }
            s = hwred(s);
            float mean = s * (1.0f / 128.0f);
            float vs = 0.0f;
#pragma unroll
            for (int j = 0; j < 8; j++) { float d = a2c[i][j] - mean; vs += d * d; }
            vs = hwred(vs);
            float inv = rsqrtf(vs * (1.0f / 128.0f) + 1e-5f);
#pragma unroll
            for (int j = 0; j < 8; j++) {
                float u = (a2c[i][j] - mean) * inv * gga[j] + bba[j];
                wbuf[(t0 + i) * 132 + c0 + j] = gelu_exact(u);
            }
        }
    }
    __syncthreads();

    // ---- layer 3: [64,10] = h2[64,128] @ W3[128,10] + b3; weighted scatter ----
    for (int o = tid; o < 64 * NOUT; o += 256) {
        int t = o / NOUT, c = o - t * NOUT;
        const float* hr = wbuf + t * 132;
        float s = w3b[c];
#pragma unroll 8
        for (int k = 0; k < H2; k++) s += hr[k] * w3s[k * NOUT + c];
        float w = swt[t];
        if (w != 0.0f) atomicAdd(y + (size_t)sidx[t] * NOUT + c, w * s);
    }
}

// ---------------- launch ----------------
extern "C" void kernel_launch(void* const* d_in, const int* in_sizes, int n_in,
                              void* d_out, int out_size) {
    const float* x    = (const float*)d_in[0];
    const float* gW1  = (const float*)d_in[1];
    const float* gb1  = (const float*)d_in[2];
    const float* glng = (const float*)d_in[3];
    const float* glnb = (const float*)d_in[4];
    const float* gW2  = (const float*)d_in[5];
    const float* gb2  = (const float*)d_in[6];
    const float* temp = (const float*)d_in[7];
    const float* eW1  = (const float*)d_in[8];
    const float* eb1  = (const float*)d_in[9];
    const float* l1g  = (const float*)d_in[10];
    const float* l1b  = (const float*)d_in[11];
    const float* eW2  = (const float*)d_in[12];
    const float* eb2  = (const float*)d_in[13];
    const float* l2g  = (const float*)d_in[14];
    const float* l2b  = (const float*)d_in[15];
    const float* eW3  = (const float*)d_in[16];
    const float* eb3  = (const float*)d_in[17];
    float* y = (float*)d_out;

    const int GATE_SMEM = (64 * 260 + 32 * 128 + 512) * 4;           // 84,992 B
    const int EXP_SMEM  = (16640 + 8512 + 1280 + 16 + 64 + 64) * 4;  // 106,304 B
    cudaFuncSetAttribute(k_gate,   cudaFuncAttributeMaxDynamicSharedMemorySize, GATE_SMEM);
    cudaFuncSetAttribute(k_expert, cudaFuncAttributeMaxDynamicSharedMemorySize, EXP_SMEM);

    k_zero<<<(N_TOK * NOUT / 2 + 255) / 256, 256>>>(y);
    k_gate<<<N_TOK / 64, 256, GATE_SMEM>>>(x, gW1, gb1, glng, glnb, gW2, gb2, temp);
    k_expert<<<dim3(N_TOK / 64, NE), 256, EXP_SMEM>>>(
        x, eW1, eb1, l1g, l1b, eW2, eb2, l2g, l2b, eW3, eb3, y);

    (void)in_sizes; (void)n_in; (void)out_size;
}

// round 14
// speedup vs baseline: 1.0380x; 1.0380x over previous
#include <cuda_runtime.h>
#include <math.h>

#define N_TOK 131072
#define DIM   256
#define GH    128
#define NE    8
#define H1    256
#define H2    128
#define NOUT  10

// ---------------- scratch (no allocations allowed) ----------------
__device__ int   g_cnt[NE];
__device__ int   g_idx[NE * N_TOK];
__device__ float g_wgt[NE * N_TOK];

typedef unsigned long long ull;

// packed fp32x2 helpers (sm_103a dual fp32 lanes; bit-identical to 2x fmaf .rn)
__device__ __forceinline__ ull pack2(float a) {
    ull r; asm("mov.b64 %0, {%1, %1};" : "=l"(r) : "f"(a)); return r;
}
__device__ __forceinline__ void ffma2(ull& d, ull a, ull b) {
    asm("fma.rn.f32x2 %0, %1, %2, %3;" : "=l"(d) : "l"(a), "l"(b), "l"(d));
}
__device__ __forceinline__ void unpack2(float& lo, float& hi, ull v) {
    asm("mov.b64 {%0, %1}, %2;" : "=f"(lo), "=f"(hi) : "l"(v));
}

__device__ __forceinline__ float gelu_exact(float v) {
    return 0.5f * v * (1.0f + erff(v * 0.70710678118654752f));
}

// reduce across a half-warp (16 lanes)
__device__ __forceinline__ float hwred(float v) {
    v += __shfl_xor_sync(0xffffffffu, v, 1);
    v += __shfl_xor_sync(0xffffffffu, v, 2);
    v += __shfl_xor_sync(0xffffffffu, v, 4);
    v += __shfl_xor_sync(0xffffffffu, v, 8);
    return v;
}

// ---------------- zero output + counters ----------------
__global__ __launch_bounds__(256) void k_zero(float* __restrict__ y) {
    int i = blockIdx.x * blockDim.x + threadIdx.x;
    if (i < (N_TOK * NOUT) / 2) ((float2*)y)[i] = make_float2(0.0f, 0.0f);
    if (i < NE) g_cnt[i] = 0;
}

// ---------------- gate ----------------
// block = 256 threads, 64 tokens. smem: xs[64][260] | ws[32*128] | lgs[512]
__global__ __launch_bounds__(256, 2) void k_gate(
    const float* __restrict__ x,
    const float* __restrict__ gW1, const float* __restrict__ gb1,
    const float* __restrict__ glng, const float* __restrict__ glnb,
    const float* __restrict__ gW2, const float* __restrict__ gb2,
    const float* __restrict__ temp)
{
    extern __shared__ float sm[];
    float* xs  = sm;             // 16640 floats
    float* ws  = xs + 64 * 260;  // 4096 floats
    float* lgs = ws + 32 * 128;  // 512 floats

    const int tid  = threadIdx.x;
    const int tok0 = blockIdx.x * 64;

    for (int i = tid; i < 4096; i += 256) {
        int r = i >> 6, c = i & 63;
        *(float4*)(xs + r * 260 + c * 4) =
            *(const float4*)(x + (size_t)(tok0 + r) * DIM + c * 4);
    }

    const int ty = tid >> 4, tx = tid & 15;
    const int t0 = ty * 4;

    ull acc2[4][4];
#pragma unroll
    for (int i = 0; i < 4; i++)
#pragma unroll
        for (int j = 0; j < 4; j++) acc2[i][j] = 0ull;

    const float* xr = xs + t0 * 260;
    for (int kc = 0; kc < DIM; kc += 32) {
        __syncthreads();
        const float4* wsrc = (const float4*)(gW1 + (size_t)kc * GH);
        for (int i = tid; i < 1024; i += 256) ((float4*)ws)[i] = wsrc[i];
        __syncthreads();
#pragma unroll 8
        for (int k = 0; k < 32; k++) {
            ull a0 = pack2(xr[0 * 260 + kc + k]);
            ull a1 = pack2(xr[1 * 260 + kc + k]);
            ull a2 = pack2(xr[2 * 260 + kc + k]);
            ull a3 = pack2(xr[3 * 260 + kc + k]);
            const ulonglong2* wr = (const ulonglong2*)(ws + k * GH + tx * 8);
            ulonglong2 p0 = wr[0], p1 = wr[1];
            ffma2(acc2[0][0], a0, p0.x); ffma2(acc2[0][1], a0, p0.y);
            ffma2(acc2[0][2], a0, p1.x); ffma2(acc2[0][3], a0, p1.y);
            ffma2(acc2[1][0], a1, p0.x); ffma2(acc2[1][1], a1, p0.y);
            ffma2(acc2[1][2], a1, p1.x); ffma2(acc2[1][3], a1, p1.y);
            ffma2(acc2[2][0], a2, p0.x); ffma2(acc2[2][1], a2, p0.y);
            ffma2(acc2[2][2], a2, p1.x); ffma2(acc2[2][3], a2, p1.y);
            ffma2(acc2[3][0], a3, p0.x); ffma2(acc2[3][1], a3, p0.y);
            ffma2(acc2[3][2], a3, p1.x); ffma2(acc2[3][3], a3, p1.y);
        }
    }
    __syncthreads();  // all xs reads done before overwrite

    // bias + LN + gelu -> store g into xs (stride 260, cols 0..127)
    {
        const int c0 = tx * 8;
        float bia[8], gga[8], bba[8];
        float4 v;
        v = *(const float4*)(gb1 + c0);     bia[0]=v.x; bia[1]=v.y; bia[2]=v.z; bia[3]=v.w;
        v = *(const float4*)(gb1 + c0 + 4); bia[4]=v.x; bia[5]=v.y; bia[6]=v.z; bia[7]=v.w;
        v = *(const float4*)(glng + c0);     gga[0]=v.x; gga[1]=v.y; gga[2]=v.z; gga[3]=v.w;
        v = *(const float4*)(glng + c0 + 4); gga[4]=v.x; gga[5]=v.y; gga[6]=v.z; gga[7]=v.w;
        v = *(const float4*)(glnb + c0);     bba[0]=v.x; bba[1]=v.y; bba[2]=v.z; bba[3]=v.w;
        v = *(const float4*)(glnb + c0 + 4); bba[4]=v.x; bba[5]=v.y; bba[6]=v.z; bba[7]=v.w;
#pragma unroll
        for (int i = 0; i < 4; i++) {
            float a[8];
#pragma unroll
            for (int j = 0; j < 4; j++) unpack2(a[2*j], a[2*j+1], acc2[i][j]);
            float s = 0.0f;
#pragma unroll
            for (int j = 0; j < 8; j++) { a[j] += bia[j]; s += a[j]; }
            s = hwred(s);
            float mean = s * (1.0f / 128.0f);
            float vs = 0.0f;
#pragma unroll
            for (int j = 0; j < 8; j++) { float d = a[j] - mean; vs += d * d; }
            vs = hwred(vs);
            float inv = rsqrtf(vs * (1.0f / 128.0f) + 1e-5f);
#pragma unroll
            for (int j = 0; j < 8; j++) {
                float u = (a[j] - mean) * inv * gga[j] + bba[j];
                xs[(t0 + i) * 260 + c0 + j] = gelu_exact(u);
            }
        }
    }
    __syncthreads();

    // gW2 -> ws (1024 floats)
    for (int i = tid; i < 256; i += 256) ((float4*)ws)[i] = ((const float4*)gW2)[i];
    __syncthreads();

    const float tt = fminf(fmaxf(temp[0], 0.5f), 5.0f);
    for (int o = tid; o < 512; o += 256) {
        int t = o >> 3, e = o & 7;
        const float* gr = xs + t * 260;
        float s = 0.0f;
#pragma unroll 8
        for (int k = 0; k < GH; k++) s += gr[k] * ws[k * NE + e];
        lgs[o] = (s + gb2[e]) / tt;
    }
    __syncthreads();

    // top-2, softmax, renorm, scatter to expert lists
    if (tid < 64) {
        float v[NE];
#pragma unroll
        for (int e = 0; e < NE; e++) v[e] = lgs[tid * NE + e];
        int i0 = 0; float b0 = v[0];
#pragma unroll
        for (int e = 1; e < NE; e++) if (v[e] > b0) { b0 = v[e]; i0 = e; }
        int i1 = -1; float b1 = -3.4e38f;
#pragma unroll
        for (int e = 0; e < NE; e++) if (e != i0 && v[e] > b1) { b1 = v[e]; i1 = e; }
        float e1 = expf(b1 - b0);
        float s = 1.0f + e1;
        float p0 = 1.0f / s, p1 = e1 / s;
        float den = p0 + p1 + 1e-10f;
        float w0 = p0 / den, w1 = p1 / den;
        int token = tok0 + tid;
        int p = atomicAdd(&g_cnt[i0], 1);
        g_idx[i0 * N_TOK + p] = token; g_wgt[i0 * N_TOK + p] = w0;
        p = atomicAdd(&g_cnt[i1], 1);
        g_idx[i1 * N_TOK + p] = token; g_wgt[i1 * N_TOK + p] = w1;
    }
}

// ---------------- expert: fused 3-layer MLP over 64 gathered tokens ----------------
__global__ __launch_bounds__(256, 2) void k_expert(
    const float* __restrict__ x,
    const float* __restrict__ eW1, const float* __restrict__ eb1,
    const float* __restrict__ l1g, const float* __restrict__ l1b,
    const float* __restrict__ eW2, const float* __restrict__ eb2,
    const float* __restrict__ l2g, const float* __restrict__ l2b,
    const float* __restrict__ eW3, const float* __restrict__ eb3,
    float* __restrict__ y)
{
    const int e   = blockIdx.y;
    const int cnt = g_cnt[e];
    const int tile = blockIdx.x;
    if (tile * 64 >= cnt) return;

    extern __shared__ float sm[];
    float* xs   = sm;               // 16640
    float* wbuf = xs + 16640;       // 8512
    float* w3s  = wbuf + 8512;      // 1280
    float* w3b  = w3s + 1280;       // 16
    float* swt  = w3b + 16;         // 64
    int*   sidx = (int*)(swt + 64); // 64

    const int tid = threadIdx.x;

    if (tid < 64) {
        int p  = tile * 64 + tid;
        int pp = p < cnt ? p : cnt - 1;
        sidx[tid] = g_idx[e * N_TOK + pp];
        swt[tid]  = (p < cnt) ? g_wgt[e * N_TOK + pp] : 0.0f;
    }
    for (int i = tid; i < 320; i += 256)
        ((float4*)w3s)[i] = ((const float4*)(eW3 + (size_t)e * H2 * NOUT))[i];
    if (tid < NOUT) w3b[tid] = eb3[e * NOUT + tid];
    __syncthreads();

    // gather x rows
    for (int i = tid; i < 4096; i += 256) {
        int r = i >> 6, c = i & 63;
        *(float4*)(xs + r * 260 + c * 4) =
            *(const float4*)(x + (size_t)sidx[r] * DIM + c * 4);
    }

    const int ty = tid >> 4, tx = tid & 15;
    const int t0 = ty * 4;
    const float* xr = xs + t0 * 260;

    // ---- layer 1: [64,256] = x[64,256] @ W1[256,256] ----
    ull acc2[4][8];
#pragma unroll
    for (int i = 0; i < 4; i++)
#pragma unroll
        for (int j = 0; j < 8; j++) acc2[i][j] = 0ull;

    for (int kc = 0; kc < DIM; kc += 32) {
        __syncthreads();
        const float4* wsrc = (const float4*)(eW1 + ((size_t)e * DIM + kc) * H1);
        for (int i = tid; i < 2048; i += 256) ((float4*)wbuf)[i] = wsrc[i];
        __syncthreads();
#pragma unroll 4
        for (int k = 0; k < 32; k++) {
            ull a0 = pack2(xr[0 * 260 + kc + k]);
            ull a1 = pack2(xr[1 * 260 + kc + k]);
            ull a2 = pack2(xr[2 * 260 + kc + k]);
            ull a3 = pack2(xr[3 * 260 + kc + k]);
            const ulonglong2* wr = (const ulonglong2*)(wbuf + k * H1 + tx * 16);
            ulonglong2 p0 = wr[0], p1 = wr[1], p2 = wr[2], p3 = wr[3];
            ffma2(acc2[0][0], a0, p0.x); ffma2(acc2[0][1], a0, p0.y);
            ffma2(acc2[0][2], a0, p1.x); ffma2(acc2[0][3], a0, p1.y);
            ffma2(acc2[0][4], a0, p2.x); ffma2(acc2[0][5], a0, p2.y);
            ffma2(acc2[0][6], a0, p3.x); ffma2(acc2[0][7], a0, p3.y);
            ffma2(acc2[1][0], a1, p0.x); ffma2(acc2[1][1], a1, p0.y);
            ffma2(acc2[1][2], a1, p1.x); ffma2(acc2[1][3], a1, p1.y);
            ffma2(acc2[1][4], a1, p2.x); ffma2(acc2[1][5], a1, p2.y);
            ffma2(acc2[1][6], a1, p3.x); ffma2(acc2[1][7], a1, p3.y);
            ffma2(acc2[2][0], a2, p0.x); ffma2(acc2[2][1], a2, p0.y);
            ffma2(acc2[2][2], a2, p1.x); ffma2(acc2[2][3], a2, p1.y);
            ffma2(acc2[2][4], a2, p2.x); ffma2(acc2[2][5], a2, p2.y);
            ffma2(acc2[2][6], a2, p3.x); ffma2(acc2[2][7], a2, p3.y);
            ffma2(acc2[3][0], a3, p0.x); ffma2(acc2[3][1], a3, p0.y);
            ffma2(acc2[3][2], a3, p1.x); ffma2(acc2[3][3], a3, p1.y);
            ffma2(acc2[3][4], a3, p2.x); ffma2(acc2[3][5], a3, p2.y);
            ffma2(acc2[3][6], a3, p3.x); ffma2(acc2[3][7], a3, p3.y);
        }
    }
    __syncthreads();  // xs reads done; safe to overwrite with h1

    // ---- LN1 + gelu -> xs ----
    {
        const int c0 = tx * 16;
        float bia[16], gga[16], bba[16];
#pragma unroll
        for (int q = 0; q < 4; q++) {
            float4 v;
            v = *(const float4*)(eb1 + e * H1 + c0 + 4 * q);
            bia[4*q]=v.x; bia[4*q+1]=v.y; bia[4*q+2]=v.z; bia[4*q+3]=v.w;
            v = *(const float4*)(l1g + e * H1 + c0 + 4 * q);
            gga[4*q]=v.x; gga[4*q+1]=v.y; gga[4*q+2]=v.z; gga[4*q+3]=v.w;
            v = *(const float4*)(l1b + e * H1 + c0 + 4 * q);
            bba[4*q]=v.x; bba[4*q+1]=v.y; bba[4*q+2]=v.z; bba[4*q+3]=v.w;
        }
#pragma unroll
        for (int i = 0; i < 4; i++) {
            float a[16];
#pragma unroll
            for (int j = 0; j < 8; j++) unpack2(a[2*j], a[2*j+1], acc2[i][j]);
            float s = 0.0f;
#pragma unroll
            for (int j = 0; j < 16; j++) { a[j] += bia[j]; s += a[j]; }
            s = hwred(s);
            float mean = s * (1.0f / 256.0f);
            float vs = 0.0f;
#pragma unroll
            for (int j = 0; j < 16; j++) { float d = a[j] - mean; vs += d * d; }
            vs = hwred(vs);
            float inv = rsqrtf(vs * (1.0f / 256.0f) + 1e-5f);
#pragma unroll
            for (int j = 0; j < 16; j++) {
                float u = (a[j] - mean) * inv * gga[j] + bba[j];
                xs[(t0 + i) * 260 + c0 + j] = gelu_exact(u);
            }
        }
    }

    // ---- layer 2: [64,128] = h1[64,256] @ W2[256,128] ----
    ull b2a[4][4];
#pragma unroll
    for (int i = 0; i < 4; i++)
#pragma unroll
        for (int j = 0; j < 4; j++) b2a[i][j] = 0ull;

    for (int kc = 0; kc < H1; kc += 32) {
        __syncthreads();
        const float4* wsrc = (const float4*)(eW2 + ((size_t)e * H1 + kc) * H2);
        for (int i = tid; i < 1024; i += 256) ((float4*)wbuf)[i] = wsrc[i];
        __syncthreads();
#pragma unroll 8
        for (int k = 0; k < 32; k++) {
            ull a0 = pack2(xr[0 * 260 + kc + k]);
            ull a1 = pack2(xr[1 * 260 + kc + k]);
            ull a2 = pack2(xr[2 * 260 + kc + k]);
            ull a3 = pack2(xr[3 * 260 + kc + k]);
            const ulonglong2* wr = (const ulonglong2*)(wbuf + k * H2 + tx * 8);
            ulonglong2 p0 = wr[0], p1 = wr[1];
            ffma2(b2a[0][0], a0, p0.x); ffma2(b2a[0][1], a0, p0.y);
            ffma2(b2a[0][2], a0, p1.x); ffma2(b2a[0][3], a0, p1.y);
            ffma2(b2a[1][0], a1, p0.x); ffma2(b2a[1][1], a1, p0.y);
            ffma2(b2a[1][2], a1, p1.x); ffma2(b2a[1][3], a1, p1.y);
            ffma2(b2a[2][0], a2, p0.x); ffma2(b2a[2][1], a2, p0.y);
            ffma2(b2a[2][2], a2, p1.x); ffma2(b2a[2][3], a2, p1.y);
            ffma2(b2a[3][0], a3, p0.x); ffma2(b2a[3][1], a3, p0.y);
            ffma2(b2a[3][2], a3, p1.x); ffma2(b2a[3][3], a3, p1.y);
        }
    }
    __syncthreads();  // wbuf reads done; safe to overwrite with h2

    // ---- LN2 + gelu -> h2 in wbuf (stride 132) ----
    {
        const int c0 = tx * 8;
        float bia[8], gga[8], bba[8];
#pragma unroll
        for (int q = 0; q < 2; q++) {
            float4 v;
            v = *(const float4*)(eb2 + e * H2 + c0 + 4 * q);
            bia[4*q]=v.x; bia[4*q+1]=v.y; bia[4*q+2]=v.z; bia[4*q+3]=v.w;
            v = *(const float4*)(l2g + e * H2 + c0 + 4 * q);
            gga[4*q]=v.x; gga[4*q+1]=v.y; gga[4*q+2]=v.z; gga[4*q+3]=v.w;
            v = *(const float4*)(l2b + e * H2 + c0 + 4 * q);
            bba[4*q]=v.x; bba[4*q+1]=v.y; bba[4*q+2]=v.z; bba[4*q+3]=v.w;
        }
#pragma unroll
        for (int i = 0; i < 4; i++) {
            float a[8];
#pragma unroll
            for (int j = 0; j < 4; j++) unpack2(a[2*j], a[2*j+1], b2a[i][j]);
            float s = 0.0f;
#pragma unroll
            for (int j = 0; j < 8; j++) { a[j] += bia[j]; s += a[j]; }
            s = hwred(s);
            float mean = s * (1.0f / 128.0f);
            float vs = 0.0f;
#pragma unroll
            for (int j = 0; j < 8; j++) { float d = a[j] - mean; vs += d * d; }
            vs = hwred(vs);
            float inv = rsqrtf(vs * (1.0f / 128.0f) + 1e-5f);
#pragma unroll
            for (int j = 0; j < 8; j++) {
                float u = (a[j] - mean) * inv * gga[j] + bba[j];
                wbuf[(t0 + i) * 132 + c0 + j] = gelu_exact(u);
            }
        }
    }
    __syncthreads();

    // ---- layer 3: [64,10] = h2[64,128] @ W3[128,10] + b3; weighted scatter ----
    for (int o = tid; o < 64 * NOUT; o += 256) {
        int t = o / NOUT, c = o - t * NOUT;
        const float* hr = wbuf + t * 132;
        float s = w3b[c];
#pragma unroll 16
        for (int k = 0; k < H2; k++) s += hr[k] * w3s[k * NOUT + c];
        float w = swt[t];
        if (w != 0.0f) atomicAdd(y + (size_t)sidx[t] * NOUT + c, w * s);
    }
}

// ---------------- launch ----------------
extern "C" void kernel_launch(void* const* d_in, const int* in_sizes, int n_in,
                              void* d_out, int out_size) {
    const float* x    = (const float*)d_in[0];
    const float* gW1  = (const float*)d_in[1];
    const float* gb1  = (const float*)d_in[2];
    const float* glng = (const float*)d_in[3];
    const float* glnb = (const float*)d_in[4];
    const float* gW2  = (const float*)d_in[5];
    const float* gb2  = (const float*)d_in[6];
    const float* temp = (const float*)d_in[7];
    const float* eW1  = (const float*)d_in[8];
    const float* eb1  = (const float*)d_in[9];
    const float* l1g  = (const float*)d_in[10];
    const float* l1b  = (const float*)d_in[11];
    const float* eW2  = (const float*)d_in[12];
    const float* eb2  = (const float*)d_in[13];
    const float* l2g  = (const float*)d_in[14];
    const float* l2b  = (const float*)d_in[15];
    const float* eW3  = (const float*)d_in[16];
    const float* eb3  = (const float*)d_in[17];
    float* y = (float*)d_out;

    const int GATE_SMEM = (64 * 260 + 32 * 128 + 512) * 4;           // 84,992 B
    const int EXP_SMEM  = (16640 + 8512 + 1280 + 16 + 64 + 64) * 4;  // 106,304 B
    cudaFuncSetAttribute(k_gate,   cudaFuncAttributeMaxDynamicSharedMemorySize, GATE_SMEM);
    cudaFuncSetAttribute(k_expert, cudaFuncAttributeMaxDynamicSharedMemorySize, EXP_SMEM);

    k_zero<<<(N_TOK * NOUT / 2 + 255) / 256, 256>>>(y);
    k_gate<<<N_TOK / 64, 256, GATE_SMEM>>>(x, gW1, gb1, glng, glnb, gW2, gb2, temp);
    k_expert<<<dim3(N_TOK / 64, NE), 256, EXP_SMEM>>>(
        x, eW1, eb1, l1g, l1b, eW2, eb2, l2g, l2b, eW3, eb3, y);

    (void)in_sizes; (void)n_in; (void)out_size;
}